// round 1
// baseline (speedup 1.0000x reference)
#include <cuda_runtime.h>
#include <cstddef>

// Problem constants
#define BATCH 32
#define NTOK  4900
#define DMODEL 256
#define HEADS 4
#define DH 64
#define WIN 49
#define RATE 5
#define NSEG 20          // NTOK / (WIN*RATE)
#define MROWS (BATCH*NTOK)   // 156800

// Scratch (allocation rules forbid cudaMalloc; use device globals)
__device__ float g_q[(size_t)MROWS * DMODEL];
__device__ float g_att[(size_t)MROWS * DMODEL];

// ---------------------------------------------------------------------------
// GEMM: C[m,n] = sum_k A[m,k] * Wt[n,k] + bias[n],  K = N = 256
// Tiles: BM=128, BN=128, BK=16; 256 threads; 8x8 outputs per thread
// (split-tile mapping: rows {trow*4..+3, 64+trow*4..+3}, cols likewise)
// ---------------------------------------------------------------------------
#define BM 128
#define BN 128
#define BK 16
#define GK 256
#define ASTRIDE (BM + 8)

__global__ __launch_bounds__(256)
void gemm_bias_kernel(const float* __restrict__ A,
                      const float* __restrict__ Wt,
                      const float* __restrict__ bias,
                      float* __restrict__ C) {
    __shared__ float As[BK][ASTRIDE];
    __shared__ float Bs[BK][ASTRIDE];

    const int tid  = threadIdx.x;
    const int trow = tid >> 4;      // 0..15
    const int tcol = tid & 15;      // 0..15
    const int mBase = blockIdx.x * BM;
    const int nBase = blockIdx.y * BN;

    const float* Ab = A + (size_t)mBase * GK;
    const float* Wb = Wt + (size_t)nBase * GK;

    float acc[8][8];
    #pragma unroll
    for (int i = 0; i < 8; i++)
        #pragma unroll
        for (int j = 0; j < 8; j++) acc[i][j] = 0.f;

    for (int k0 = 0; k0 < GK; k0 += BK) {
        // Load A/B tiles: 128 rows x 16 k = 512 float4 each; 2 per thread
        #pragma unroll
        for (int l = 0; l < 2; l++) {
            int idx = tid + l * 256;       // 0..511
            int r   = idx >> 2;            // 0..127
            int c   = (idx & 3) << 2;      // 0,4,8,12
            float4 va = *reinterpret_cast<const float4*>(Ab + (size_t)r * GK + k0 + c);
            As[c + 0][r] = va.x; As[c + 1][r] = va.y;
            As[c + 2][r] = va.z; As[c + 3][r] = va.w;
            float4 vb = *reinterpret_cast<const float4*>(Wb + (size_t)r * GK + k0 + c);
            Bs[c + 0][r] = vb.x; Bs[c + 1][r] = vb.y;
            Bs[c + 2][r] = vb.z; Bs[c + 3][r] = vb.w;
        }
        __syncthreads();

        #pragma unroll
        for (int kk = 0; kk < BK; kk++) {
            float4 a0 = *reinterpret_cast<const float4*>(&As[kk][trow * 4]);
            float4 a1 = *reinterpret_cast<const float4*>(&As[kk][64 + trow * 4]);
            float4 b0 = *reinterpret_cast<const float4*>(&Bs[kk][tcol * 4]);
            float4 b1 = *reinterpret_cast<const float4*>(&Bs[kk][64 + tcol * 4]);
            float ra[8] = {a0.x, a0.y, a0.z, a0.w, a1.x, a1.y, a1.z, a1.w};
            float rb[8] = {b0.x, b0.y, b0.z, b0.w, b1.x, b1.y, b1.z, b1.w};
            #pragma unroll
            for (int i = 0; i < 8; i++)
                #pragma unroll
                for (int j = 0; j < 8; j++)
                    acc[i][j] += ra[i] * rb[j];
        }
        __syncthreads();
    }

    // Bias cache for this thread's 8 columns
    float bcache[8];
    #pragma unroll
    for (int hn = 0; hn < 2; hn++)
        #pragma unroll
        for (int j = 0; j < 4; j++)
            bcache[hn * 4 + j] = bias[nBase + hn * 64 + tcol * 4 + j];

    #pragma unroll
    for (int hm = 0; hm < 2; hm++)
        #pragma unroll
        for (int i = 0; i < 4; i++) {
            int m = mBase + hm * 64 + trow * 4 + i;
            #pragma unroll
            for (int hn = 0; hn < 2; hn++) {
                int n = nBase + hn * 64 + tcol * 4;
                int ai = hm * 4 + i;
                float4 v;
                v.x = acc[ai][hn * 4 + 0] + bcache[hn * 4 + 0];
                v.y = acc[ai][hn * 4 + 1] + bcache[hn * 4 + 1];
                v.z = acc[ai][hn * 4 + 2] + bcache[hn * 4 + 2];
                v.w = acc[ai][hn * 4 + 3] + bcache[hn * 4 + 3];
                *reinterpret_cast<float4*>(C + (size_t)m * GK + n) = v;
            }
        }
}

// ---------------------------------------------------------------------------
// Attention: one block per (b, g, r, h). Tile x = q[49 tokens, 64 dims].
// scores = scale * x x^T -> softmax rows -> out = P x.
// 256 threads = 8 warps; warp w owns rows {w, w+8, ...}; 4-row register
// blocking so FFMA (not the smem crossbar) is the limiting pipe.
// xs4 row stride = 17 float4 (68 floats)  -> conflict-free column reads.
// ---------------------------------------------------------------------------
__global__ __launch_bounds__(256)
void attn_kernel(const float* __restrict__ q, float* __restrict__ out) {
    // decode (b,g,r,h) from blockIdx.x   (idx = ((b*20+g)*5+r)*4+h)
    int idx = blockIdx.x;
    int h  = idx & 3;
    int r  = (idx >> 2) % RATE;
    int gg = (idx / (RATE * HEADS)) % NSEG;
    int b  = idx / (RATE * HEADS * NSEG);

    __shared__ float4 xs4[64 * 17];     // rows padded to 64 (OOB-safe garbage)
    __shared__ float  ps[64 * 52];

    const size_t rowBase = ((size_t)b * NTOK + (size_t)gg * (WIN * RATE) + r);
    const float* base = q + rowBase * DMODEL + h * DH;
    float* obase = out + rowBase * DMODEL + h * DH;

    const int tid = threadIdx.x;
    // Stage tile: 49 rows x 16 float4
    for (int t = tid; t < WIN * 16; t += 256) {
        int row = t >> 4, c = t & 15;
        xs4[row * 17 + c] =
            *reinterpret_cast<const float4*>(base + (size_t)row * (RATE * DMODEL) + c * 4);
    }
    __syncthreads();

    const int warp = tid >> 5, lane = tid & 31;
    const float scale = 0.125f;             // dh^-0.5
    const bool vj1 = (lane + 32) < WIN;     // lane < 17
    const int jj1 = vj1 ? (lane + 32) : lane;

    // ---- Phase 2: scores + softmax ----
    for (int i0 = warp; i0 < WIN; i0 += 32) {
        int rows[4] = {i0, i0 + 8, i0 + 16, i0 + 24};
        float s0[4] = {0.f, 0.f, 0.f, 0.f};
        float s1[4] = {0.f, 0.f, 0.f, 0.f};
        #pragma unroll
        for (int kk = 0; kk < 16; kk++) {
            float4 xj0 = xs4[lane * 17 + kk];
            float4 xj1 = xs4[jj1 * 17 + kk];
            #pragma unroll
            for (int t = 0; t < 4; t++) {
                float4 qv = xs4[rows[t] * 17 + kk];
                s0[t] += qv.x * xj0.x + qv.y * xj0.y + qv.z * xj0.z + qv.w * xj0.w;
                s1[t] += qv.x * xj1.x + qv.y * xj1.y + qv.z * xj1.z + qv.w * xj1.w;
            }
        }
        #pragma unroll
        for (int t = 0; t < 4; t++) {
            if (rows[t] >= WIN) break;          // uniform across warp
            float a0 = s0[t] * scale;
            float a1 = s1[t] * scale;
            float m = vj1 ? fmaxf(a0, a1) : a0;
            #pragma unroll
            for (int o = 16; o; o >>= 1) m = fmaxf(m, __shfl_xor_sync(0xffffffffu, m, o));
            float e0 = __expf(a0 - m);
            float e1 = vj1 ? __expf(a1 - m) : 0.f;
            float s = e0 + e1;
            #pragma unroll
            for (int o = 16; o; o >>= 1) s += __shfl_xor_sync(0xffffffffu, s, o);
            float inv = 1.f / s;
            ps[rows[t] * 52 + lane] = e0 * inv;
            if (vj1) ps[rows[t] * 52 + lane + 32] = e1 * inv;
        }
    }
    __syncwarp();   // ps rows are private to the owning warp; order writes->reads

    // ---- Phase 3: out = P @ X ----
    const float2* xs2 = reinterpret_cast<const float2*>(xs4);   // row stride 34
    for (int i0 = warp; i0 < WIN; i0 += 32) {
        int rows[4] = {i0, i0 + 8, i0 + 16, i0 + 24};
        float2 o[4] = {{0.f, 0.f}, {0.f, 0.f}, {0.f, 0.f}, {0.f, 0.f}};
        #pragma unroll 7
        for (int j = 0; j < WIN; j++) {
            float2 v = xs2[j * 34 + lane];
            #pragma unroll
            for (int t = 0; t < 4; t++) {
                float p = ps[rows[t] * 52 + j];
                o[t].x += p * v.x;
                o[t].y += p * v.y;
            }
        }
        #pragma unroll
        for (int t = 0; t < 4; t++) {
            if (rows[t] >= WIN) break;
            *reinterpret_cast<float2*>(obase + (size_t)rows[t] * (RATE * DMODEL) + 2 * lane) = o[t];
        }
    }
}

// ---------------------------------------------------------------------------
// Launch: proj1 -> windowed attention -> proj2
// ---------------------------------------------------------------------------
extern "C" void kernel_launch(void* const* d_in, const int* in_sizes, int n_in,
                              void* d_out, int out_size) {
    const float* emb = (const float*)d_in[0];
    const float* Wq  = (const float*)d_in[1];
    const float* bq  = (const float*)d_in[2];
    const float* Wo  = (const float*)d_in[3];
    const float* bo  = (const float*)d_in[4];
    float* outp = (float*)d_out;

    float *qbuf = nullptr, *abuf = nullptr;
    cudaGetSymbolAddress((void**)&qbuf, g_q);
    cudaGetSymbolAddress((void**)&abuf, g_att);

    dim3 ggrid(MROWS / BM, DMODEL / BN);   // (1225, 2)
    gemm_bias_kernel<<<ggrid, 256>>>(emb, Wq, bq, qbuf);
    attn_kernel<<<BATCH * NSEG * RATE * HEADS, 256>>>(qbuf, abuf);
    gemm_bias_kernel<<<ggrid, 256>>>(abuf, Wo, bo, outp);
}

// round 2
// speedup vs baseline: 1.3881x; 1.3881x over previous
#include <cuda_runtime.h>
#include <cstddef>
#include <cstdint>

// Problem constants
#define BATCH 32
#define NTOK  4900
#define DMODEL 256
#define HEADS 4
#define DH 64
#define WIN 49
#define RATE 5
#define NSEG 20          // NTOK / (WIN*RATE)
#define MROWS (BATCH*NTOK)   // 156800

// Scratch (allocation rules forbid cudaMalloc; use device globals)
__device__ float g_q[(size_t)MROWS * DMODEL];
__device__ float g_att[(size_t)MROWS * DMODEL];

// ---------------------------------------------------------------------------
// TF32 tensor-core GEMM:  C[m,n] = sum_k A[m,k]*Wt[n,k] + bias[n]
//   M = 156800, N = K = 256. BM=BN=128, BK=32, 256 threads (8 warps),
//   warp tile 64x32 (warp grid 2x4), mma.sync.m16n8k8.tf32, fp32 accum.
//   SMEM holds A/B pre-permuted in fragment order:
//     A frag slot  [ks][mt][lane] -> float4 {a0,a1,a2,a3}   (LDS.128)
//     B frag slot  [ks][nt][lane] -> float2 {b0,b1}         (LDS.64)
//   Double-buffered (4x16KB = 64KB dynamic smem).
// ---------------------------------------------------------------------------

__device__ __forceinline__ uint32_t to_tf32(float x) {
    uint32_t y;
    asm("cvt.rna.tf32.f32 %0, %1;" : "=r"(y) : "f"(x));
    return y;
}

__device__ __forceinline__ void mma_tf32(float* c, const float4& a, const float2& b) {
    const uint32_t* ap = reinterpret_cast<const uint32_t*>(&a);
    const uint32_t* bp = reinterpret_cast<const uint32_t*>(&b);
    asm volatile(
        "mma.sync.aligned.m16n8k8.row.col.f32.tf32.tf32.f32 "
        "{%0,%1,%2,%3}, {%4,%5,%6,%7}, {%8,%9}, {%0,%1,%2,%3};\n"
        : "+f"(c[0]), "+f"(c[1]), "+f"(c[2]), "+f"(c[3])
        : "r"(ap[0]), "r"(ap[1]), "r"(ap[2]), "r"(ap[3]),
          "r"(bp[0]), "r"(bp[1]));
}

#define GK 256

// global -> registers (one BK=32 chunk; 4 float4 of A and of B per thread)
__device__ __forceinline__ void gload(const float* __restrict__ Ab,
                                      const float* __restrict__ Wb,
                                      int tid, int kc, float4* ra, float4* rb) {
    #pragma unroll
    for (int l = 0; l < 4; l++) {
        int idx = l * 256 + tid;          // 0..1023
        int m   = idx >> 3;               // 0..127 (row / n-row)
        int kq  = idx & 7;                // float4 within 32-k chunk
        ra[l] = *reinterpret_cast<const float4*>(Ab + (size_t)m * GK + kc * 32 + kq * 4);
        rb[l] = *reinterpret_cast<const float4*>(Wb + (size_t)m * GK + kc * 32 + kq * 4);
    }
}

// registers -> smem (fragment-order permutation, with tf32 rounding)
__device__ __forceinline__ void sstore(float* As, float* Bs, int tid,
                                       const float4* ra, const float4* rb) {
    #pragma unroll
    for (int l = 0; l < 4; l++) {
        int idx = l * 256 + tid;
        int m   = idx >> 3;
        int kq  = idx & 7;
        int ks  = kq >> 1;                // 0..3 : which k8-step
        int kh  = kq & 1;                 // k half within step (cols 0-3 / 4-7)
        // A fragment placement
        int mt = m >> 4, r8 = (m >> 3) & 1, r = m & 7;
        int abase = (ks * 8 + mt) * 32 + r * 4;
        int areg  = r8 + 2 * kh;
        const float* av = reinterpret_cast<const float*>(&ra[l]);
        uint32_t* Au = reinterpret_cast<uint32_t*>(As);
        #pragma unroll
        for (int cc = 0; cc < 4; cc++)
            Au[(abase + cc) * 4 + areg] = to_tf32(av[cc]);
        // B fragment placement (m plays the role of n)
        int nt = m >> 3, nr = m & 7;
        int bbase = (ks * 16 + nt) * 32 + nr * 4;
        const float* bv = reinterpret_cast<const float*>(&rb[l]);
        uint32_t* Bu = reinterpret_cast<uint32_t*>(Bs);
        #pragma unroll
        for (int cc = 0; cc < 4; cc++)
            Bu[(bbase + cc) * 2 + kh] = to_tf32(bv[cc]);
    }
}

__global__ __launch_bounds__(256)
void gemm_tf32_kernel(const float* __restrict__ A,
                      const float* __restrict__ Wt,
                      const float* __restrict__ bias,
                      float* __restrict__ C) {
    extern __shared__ float smem[];
    float* AsBuf[2] = {smem,        smem + 4096};
    float* BsBuf[2] = {smem + 8192, smem + 12288};

    const int tid  = threadIdx.x;
    const int warp = tid >> 5, lane = tid & 31;
    const int wm = warp >> 2;     // 0..1  -> 64 rows
    const int wn = warp & 3;      // 0..3  -> 32 cols
    const int mBase = blockIdx.x * 128;
    const int nBase = blockIdx.y * 128;

    const float* Ab = A + (size_t)mBase * GK;
    const float* Wb = Wt + (size_t)nBase * GK;

    float c[4][4][4];
    #pragma unroll
    for (int i = 0; i < 4; i++)
        #pragma unroll
        for (int j = 0; j < 4; j++)
            #pragma unroll
            for (int r = 0; r < 4; r++) c[i][j][r] = 0.f;

    float4 ra[4], rb[4];
    gload(Ab, Wb, tid, 0, ra, rb);
    sstore(AsBuf[0], BsBuf[0], tid, ra, rb);
    __syncthreads();

    #pragma unroll 1
    for (int kc = 0; kc < 8; kc++) {
        int cur = kc & 1;
        if (kc < 7) gload(Ab, Wb, tid, kc + 1, ra, rb);

        const float* As = AsBuf[cur];
        const float* Bs = BsBuf[cur];
        #pragma unroll
        for (int ks = 0; ks < 4; ks++) {
            float4 af[4];
            float2 bf[4];
            #pragma unroll
            for (int i = 0; i < 4; i++)
                af[i] = *reinterpret_cast<const float4*>(
                    &As[((ks * 8 + wm * 4 + i) * 32 + lane) * 4]);
            #pragma unroll
            for (int j = 0; j < 4; j++)
                bf[j] = *reinterpret_cast<const float2*>(
                    &Bs[((ks * 16 + wn * 4 + j) * 32 + lane) * 2]);
            #pragma unroll
            for (int i = 0; i < 4; i++)
                #pragma unroll
                for (int j = 0; j < 4; j++)
                    mma_tf32(c[i][j], af[i], bf[j]);
        }

        if (kc < 7) sstore(AsBuf[cur ^ 1], BsBuf[cur ^ 1], tid, ra, rb);
        __syncthreads();
    }

    // Epilogue: add bias, write fp32
    #pragma unroll
    for (int j = 0; j < 4; j++) {
        int col = nBase + wn * 32 + j * 8 + (lane & 3) * 2;
        float b0 = bias[col], b1 = bias[col + 1];
        #pragma unroll
        for (int i = 0; i < 4; i++) {
            int row0 = mBase + wm * 64 + i * 16 + (lane >> 2);
            float2 v0 = {c[i][j][0] + b0, c[i][j][1] + b1};
            float2 v1 = {c[i][j][2] + b0, c[i][j][3] + b1};
            *reinterpret_cast<float2*>(C + (size_t)row0 * GK + col) = v0;
            *reinterpret_cast<float2*>(C + (size_t)(row0 + 8) * GK + col) = v1;
        }
    }
}

// ---------------------------------------------------------------------------
// Attention: one block per (b, g, r, h) — unchanged from R1 baseline.
// ---------------------------------------------------------------------------
__global__ __launch_bounds__(256)
void attn_kernel(const float* __restrict__ q, float* __restrict__ out) {
    int idx = blockIdx.x;
    int h  = idx & 3;
    int r  = (idx >> 2) % RATE;
    int gg = (idx / (RATE * HEADS)) % NSEG;
    int b  = idx / (RATE * HEADS * NSEG);

    __shared__ float4 xs4[64 * 17];
    __shared__ float  ps[64 * 52];

    const size_t rowBase = ((size_t)b * NTOK + (size_t)gg * (WIN * RATE) + r);
    const float* base = q + rowBase * DMODEL + h * DH;
    float* obase = out + rowBase * DMODEL + h * DH;

    const int tid = threadIdx.x;
    for (int t = tid; t < WIN * 16; t += 256) {
        int row = t >> 4, c = t & 15;
        xs4[row * 17 + c] =
            *reinterpret_cast<const float4*>(base + (size_t)row * (RATE * DMODEL) + c * 4);
    }
    __syncthreads();

    const int warp = tid >> 5, lane = tid & 31;
    const float scale = 0.125f;
    const bool vj1 = (lane + 32) < WIN;
    const int jj1 = vj1 ? (lane + 32) : lane;

    for (int i0 = warp; i0 < WIN; i0 += 32) {
        int rows[4] = {i0, i0 + 8, i0 + 16, i0 + 24};
        float s0[4] = {0.f, 0.f, 0.f, 0.f};
        float s1[4] = {0.f, 0.f, 0.f, 0.f};
        #pragma unroll
        for (int kk = 0; kk < 16; kk++) {
            float4 xj0 = xs4[lane * 17 + kk];
            float4 xj1 = xs4[jj1 * 17 + kk];
            #pragma unroll
            for (int t = 0; t < 4; t++) {
                float4 qv = xs4[rows[t] * 17 + kk];
                s0[t] += qv.x * xj0.x + qv.y * xj0.y + qv.z * xj0.z + qv.w * xj0.w;
                s1[t] += qv.x * xj1.x + qv.y * xj1.y + qv.z * xj1.z + qv.w * xj1.w;
            }
        }
        #pragma unroll
        for (int t = 0; t < 4; t++) {
            if (rows[t] >= WIN) break;
            float a0 = s0[t] * scale;
            float a1 = s1[t] * scale;
            float m = vj1 ? fmaxf(a0, a1) : a0;
            #pragma unroll
            for (int o = 16; o; o >>= 1) m = fmaxf(m, __shfl_xor_sync(0xffffffffu, m, o));
            float e0 = __expf(a0 - m);
            float e1 = vj1 ? __expf(a1 - m) : 0.f;
            float s = e0 + e1;
            #pragma unroll
            for (int o = 16; o; o >>= 1) s += __shfl_xor_sync(0xffffffffu, s, o);
            float inv = 1.f / s;
            ps[rows[t] * 52 + lane] = e0 * inv;
            if (vj1) ps[rows[t] * 52 + lane + 32] = e1 * inv;
        }
    }
    __syncwarp();

    const float2* xs2 = reinterpret_cast<const float2*>(xs4);
    for (int i0 = warp; i0 < WIN; i0 += 32) {
        int rows[4] = {i0, i0 + 8, i0 + 16, i0 + 24};
        float2 o[4] = {{0.f, 0.f}, {0.f, 0.f}, {0.f, 0.f}, {0.f, 0.f}};
        #pragma unroll 7
        for (int j = 0; j < WIN; j++) {
            float2 v = xs2[j * 34 + lane];
            #pragma unroll
            for (int t = 0; t < 4; t++) {
                float p = ps[rows[t] * 52 + j];
                o[t].x += p * v.x;
                o[t].y += p * v.y;
            }
        }
        #pragma unroll
        for (int t = 0; t < 4; t++) {
            if (rows[t] >= WIN) break;
            *reinterpret_cast<float2*>(obase + (size_t)rows[t] * (RATE * DMODEL) + 2 * lane) = o[t];
        }
    }
}

// ---------------------------------------------------------------------------
// Launch: proj1 (tf32 mma) -> windowed attention -> proj2 (tf32 mma)
// ---------------------------------------------------------------------------
extern "C" void kernel_launch(void* const* d_in, const int* in_sizes, int n_in,
                              void* d_out, int out_size) {
    const float* emb = (const float*)d_in[0];
    const float* Wq  = (const float*)d_in[1];
    const float* bq  = (const float*)d_in[2];
    const float* Wo  = (const float*)d_in[3];
    const float* bo  = (const float*)d_in[4];
    float* outp = (float*)d_out;

    float *qbuf = nullptr, *abuf = nullptr;
    cudaGetSymbolAddress((void**)&qbuf, g_q);
    cudaGetSymbolAddress((void**)&abuf, g_att);

    const int smemBytes = 64 * 1024;
    static bool attrSet = false;
    if (!attrSet) {
        cudaFuncSetAttribute(gemm_tf32_kernel,
                             cudaFuncAttributeMaxDynamicSharedMemorySize, smemBytes);
        attrSet = true;
    }

    dim3 ggrid(MROWS / 128, DMODEL / 128);   // (1225, 2)
    gemm_tf32_kernel<<<ggrid, 256, smemBytes>>>(emb, Wq, bq, qbuf);
    attn_kernel<<<BATCH * NSEG * RATE * HEADS, 256>>>(qbuf, abuf);
    gemm_tf32_kernel<<<ggrid, 256, smemBytes>>>(abuf, Wo, bo, outp);
}

// round 3
// speedup vs baseline: 2.7600x; 1.9883x over previous
#include <cuda_runtime.h>
#include <cstddef>
#include <cstdint>

// Problem constants
#define BATCH 32
#define NTOK  4900
#define DMODEL 256
#define HEADS 4
#define DH 64
#define WIN 49
#define RATE 5
#define NSEG 20          // NTOK / (WIN*RATE)
#define MROWS (BATCH*NTOK)   // 156800

__device__ float g_q[(size_t)MROWS * DMODEL];
__device__ float g_att[(size_t)MROWS * DMODEL];

__device__ __forceinline__ uint32_t to_tf32(float x) {
    uint32_t y;
    asm("cvt.rna.tf32.f32 %0, %1;" : "=r"(y) : "f"(x));
    return y;
}

__device__ __forceinline__ void mma_tf32_r(float* c,
                                           uint32_t a0, uint32_t a1, uint32_t a2, uint32_t a3,
                                           uint32_t b0, uint32_t b1) {
    asm volatile(
        "mma.sync.aligned.m16n8k8.row.col.f32.tf32.tf32.f32 "
        "{%0,%1,%2,%3}, {%4,%5,%6,%7}, {%8,%9}, {%0,%1,%2,%3};\n"
        : "+f"(c[0]), "+f"(c[1]), "+f"(c[2]), "+f"(c[3])
        : "r"(a0), "r"(a1), "r"(a2), "r"(a3), "r"(b0), "r"(b1));
}

// ---------------------------------------------------------------------------
// TF32 tensor-core GEMM (unchanged from R2): C = A @ Wt^T + bias
// ---------------------------------------------------------------------------
#define GK 256

__device__ __forceinline__ void mma_tf32(float* c, const float4& a, const float2& b) {
    const uint32_t* ap = reinterpret_cast<const uint32_t*>(&a);
    const uint32_t* bp = reinterpret_cast<const uint32_t*>(&b);
    asm volatile(
        "mma.sync.aligned.m16n8k8.row.col.f32.tf32.tf32.f32 "
        "{%0,%1,%2,%3}, {%4,%5,%6,%7}, {%8,%9}, {%0,%1,%2,%3};\n"
        : "+f"(c[0]), "+f"(c[1]), "+f"(c[2]), "+f"(c[3])
        : "r"(ap[0]), "r"(ap[1]), "r"(ap[2]), "r"(ap[3]),
          "r"(bp[0]), "r"(bp[1]));
}

__device__ __forceinline__ void gload(const float* __restrict__ Ab,
                                      const float* __restrict__ Wb,
                                      int tid, int kc, float4* ra, float4* rb) {
    #pragma unroll
    for (int l = 0; l < 4; l++) {
        int idx = l * 256 + tid;
        int m   = idx >> 3;
        int kq  = idx & 7;
        ra[l] = *reinterpret_cast<const float4*>(Ab + (size_t)m * GK + kc * 32 + kq * 4);
        rb[l] = *reinterpret_cast<const float4*>(Wb + (size_t)m * GK + kc * 32 + kq * 4);
    }
}

__device__ __forceinline__ void sstore(float* As, float* Bs, int tid,
                                       const float4* ra, const float4* rb) {
    #pragma unroll
    for (int l = 0; l < 4; l++) {
        int idx = l * 256 + tid;
        int m   = idx >> 3;
        int kq  = idx & 7;
        int ks  = kq >> 1;
        int kh  = kq & 1;
        int mt = m >> 4, r8 = (m >> 3) & 1, r = m & 7;
        int abase = (ks * 8 + mt) * 32 + r * 4;
        int areg  = r8 + 2 * kh;
        const float* av = reinterpret_cast<const float*>(&ra[l]);
        uint32_t* Au = reinterpret_cast<uint32_t*>(As);
        #pragma unroll
        for (int cc = 0; cc < 4; cc++)
            Au[(abase + cc) * 4 + areg] = to_tf32(av[cc]);
        int nt = m >> 3, nr = m & 7;
        int bbase = (ks * 16 + nt) * 32 + nr * 4;
        const float* bv = reinterpret_cast<const float*>(&rb[l]);
        uint32_t* Bu = reinterpret_cast<uint32_t*>(Bs);
        #pragma unroll
        for (int cc = 0; cc < 4; cc++)
            Bu[(bbase + cc) * 2 + kh] = to_tf32(bv[cc]);
    }
}

__global__ __launch_bounds__(256)
void gemm_tf32_kernel(const float* __restrict__ A,
                      const float* __restrict__ Wt,
                      const float* __restrict__ bias,
                      float* __restrict__ C) {
    extern __shared__ float smem[];
    float* AsBuf[2] = {smem,        smem + 4096};
    float* BsBuf[2] = {smem + 8192, smem + 12288};

    const int tid  = threadIdx.x;
    const int warp = tid >> 5, lane = tid & 31;
    const int wm = warp >> 2;
    const int wn = warp & 3;
    const int mBase = blockIdx.x * 128;
    const int nBase = blockIdx.y * 128;

    const float* Ab = A + (size_t)mBase * GK;
    const float* Wb = Wt + (size_t)nBase * GK;

    float c[4][4][4];
    #pragma unroll
    for (int i = 0; i < 4; i++)
        #pragma unroll
        for (int j = 0; j < 4; j++)
            #pragma unroll
            for (int r = 0; r < 4; r++) c[i][j][r] = 0.f;

    float4 ra[4], rb[4];
    gload(Ab, Wb, tid, 0, ra, rb);
    sstore(AsBuf[0], BsBuf[0], tid, ra, rb);
    __syncthreads();

    #pragma unroll 1
    for (int kc = 0; kc < 8; kc++) {
        int cur = kc & 1;
        if (kc < 7) gload(Ab, Wb, tid, kc + 1, ra, rb);

        const float* As = AsBuf[cur];
        const float* Bs = BsBuf[cur];
        #pragma unroll
        for (int ks = 0; ks < 4; ks++) {
            float4 af[4];
            float2 bf[4];
            #pragma unroll
            for (int i = 0; i < 4; i++)
                af[i] = *reinterpret_cast<const float4*>(
                    &As[((ks * 8 + wm * 4 + i) * 32 + lane) * 4]);
            #pragma unroll
            for (int j = 0; j < 4; j++)
                bf[j] = *reinterpret_cast<const float2*>(
                    &Bs[((ks * 16 + wn * 4 + j) * 32 + lane) * 2]);
            #pragma unroll
            for (int i = 0; i < 4; i++)
                #pragma unroll
                for (int j = 0; j < 4; j++)
                    mma_tf32(c[i][j], af[i], bf[j]);
        }

        if (kc < 7) sstore(AsBuf[cur ^ 1], BsBuf[cur ^ 1], tid, ra, rb);
        __syncthreads();
    }

    #pragma unroll
    for (int j = 0; j < 4; j++) {
        int col = nBase + wn * 32 + j * 8 + (lane & 3) * 2;
        float b0 = bias[col], b1 = bias[col + 1];
        #pragma unroll
        for (int i = 0; i < 4; i++) {
            int row0 = mBase + wm * 64 + i * 16 + (lane >> 2);
            float2 v0 = {c[i][j][0] + b0, c[i][j][1] + b1};
            float2 v1 = {c[i][j][2] + b0, c[i][j][3] + b1};
            *reinterpret_cast<float2*>(C + (size_t)row0 * GK + col) = v0;
            *reinterpret_cast<float2*>(C + (size_t)(row0 + 8) * GK + col) = v1;
        }
    }
}

// ---------------------------------------------------------------------------
// Tensor-core attention: one block per (b,g,r,h), 128 threads (4 warps).
// X tile 49x64 padded to 64x64, staged as tf32 in Xs (row-major) and
// Xt (transposed, for the PV B operand). scores = X X^T via m16n8k8.tf32
// (NT: both frags from Xs rows); softmax in C-fragment registers; P is
// converted C-layout -> A-layout with intra-quad shuffles; PV against Xt.
// Row stride 68 words => LDS bank = 4*row+col : conflict-free frag loads.
// ---------------------------------------------------------------------------
__global__ __launch_bounds__(128)
void attn_mma_kernel(const float* __restrict__ q, float* __restrict__ out) {
    __shared__ uint32_t Xs[64][68];
    __shared__ uint32_t Xt[64][68];

    int idx = blockIdx.x;
    int h  = idx & 3;
    int r  = (idx >> 2) % RATE;
    int gg = (idx / (RATE * HEADS)) % NSEG;
    int b  = idx / (RATE * HEADS * NSEG);

    const size_t rowBase = ((size_t)b * NTOK + (size_t)gg * (WIN * RATE) + r);
    const float* base = q + rowBase * DMODEL + h * DH;
    float* obase = out + rowBase * DMODEL + h * DH;

    const int tid  = threadIdx.x;
    const int warp = tid >> 5, lane = tid & 31;
    const int qd = lane >> 2, qq = lane & 3;

    // Zero padding: Xs rows 49..63; Xt cols 49..63 (avoid NaN garbage in pads)
    for (int t = tid; t < 15 * 68; t += 128) {
        int rr = t / 68;
        Xs[49 + rr][t - rr * 68] = 0;
    }
    for (int t = tid; t < 64 * 15; t += 128) {
        int d = t / 15;
        Xt[d][49 + (t - d * 15)] = 0;
    }

    // Stage 49x64 tile (16 float4 per row), converting to tf32; fill Xs + Xt
    for (int t = tid; t < WIN * 16; t += 128) {
        int row = t >> 4, c4 = t & 15;
        float4 v = *reinterpret_cast<const float4*>(
            base + (size_t)row * (RATE * DMODEL) + c4 * 4);
        uint32_t u0 = to_tf32(v.x), u1 = to_tf32(v.y);
        uint32_t u2 = to_tf32(v.z), u3 = to_tf32(v.w);
        *reinterpret_cast<uint4*>(&Xs[row][c4 * 4]) = make_uint4(u0, u1, u2, u3);
        Xt[c4 * 4 + 0][row] = u0;
        Xt[c4 * 4 + 1][row] = u1;
        Xt[c4 * 4 + 2][row] = u2;
        Xt[c4 * 4 + 3][row] = u3;
    }
    __syncthreads();

    const int mrow = warp * 16;

    // ---- scores = X @ X^T (rows mrow..mrow+15, all 64 cols) ----
    float c[8][4];
    #pragma unroll
    for (int nt = 0; nt < 8; nt++)
        #pragma unroll
        for (int k = 0; k < 4; k++) c[nt][k] = 0.f;

    #pragma unroll
    for (int ks = 0; ks < 8; ks++) {
        uint32_t a0 = Xs[mrow + qd][ks * 8 + qq];
        uint32_t a1 = Xs[mrow + qd + 8][ks * 8 + qq];
        uint32_t a2 = Xs[mrow + qd][ks * 8 + qq + 4];
        uint32_t a3 = Xs[mrow + qd + 8][ks * 8 + qq + 4];
        #pragma unroll
        for (int nt = 0; nt < 8; nt++) {
            uint32_t b0 = Xs[nt * 8 + qd][ks * 8 + qq];
            uint32_t b1 = Xs[nt * 8 + qd][ks * 8 + qq + 4];
            mma_tf32_r(c[nt], a0, a1, a2, a3, b0, b1);
        }
    }

    // ---- mask + softmax in fragments ----
    const float scale = 0.125f;
    const float NEG = __int_as_float(0xff800000);   // -inf
    float m0 = NEG, m1 = NEG;
    #pragma unroll
    for (int nt = 0; nt < 8; nt++) {
        #pragma unroll
        for (int par = 0; par < 2; par++) {
            int j = nt * 8 + 2 * qq + par;
            float v0 = (j < WIN) ? c[nt][par] * scale : NEG;
            float v1 = (j < WIN) ? c[nt][par + 2] * scale : NEG;
            c[nt][par] = v0;
            c[nt][par + 2] = v1;
            m0 = fmaxf(m0, v0);
            m1 = fmaxf(m1, v1);
        }
    }
    m0 = fmaxf(m0, __shfl_xor_sync(0xffffffffu, m0, 1));
    m0 = fmaxf(m0, __shfl_xor_sync(0xffffffffu, m0, 2));
    m1 = fmaxf(m1, __shfl_xor_sync(0xffffffffu, m1, 1));
    m1 = fmaxf(m1, __shfl_xor_sync(0xffffffffu, m1, 2));

    float s0 = 0.f, s1 = 0.f;
    #pragma unroll
    for (int nt = 0; nt < 8; nt++) {
        #pragma unroll
        for (int par = 0; par < 2; par++) {
            float e0 = __expf(c[nt][par] - m0);
            float e1 = __expf(c[nt][par + 2] - m1);
            c[nt][par] = e0;
            c[nt][par + 2] = e1;
            s0 += e0;
            s1 += e1;
        }
    }
    s0 += __shfl_xor_sync(0xffffffffu, s0, 1);
    s0 += __shfl_xor_sync(0xffffffffu, s0, 2);
    s1 += __shfl_xor_sync(0xffffffffu, s1, 1);
    s1 += __shfl_xor_sync(0xffffffffu, s1, 2);
    float inv0 = 1.f / s0, inv1 = 1.f / s1;

    // ---- PV: out = P @ X (P from C-frags via quad shuffles, B from Xt) ----
    float o[8][4];
    #pragma unroll
    for (int nt = 0; nt < 8; nt++)
        #pragma unroll
        for (int k = 0; k < 4; k++) o[nt][k] = 0.f;

    const int srcA = (lane & ~3) + (qq >> 1);
    const bool odd = (qq & 1);

    #pragma unroll
    for (int ks = 0; ks < 8; ks++) {
        float v0 = __shfl_sync(0xffffffffu, c[ks][0], srcA);
        float v1 = __shfl_sync(0xffffffffu, c[ks][1], srcA);
        float v2 = __shfl_sync(0xffffffffu, c[ks][2], srcA);
        float v3 = __shfl_sync(0xffffffffu, c[ks][3], srcA);
        float w0 = __shfl_sync(0xffffffffu, c[ks][0], srcA + 2);
        float w1 = __shfl_sync(0xffffffffu, c[ks][1], srcA + 2);
        float w2 = __shfl_sync(0xffffffffu, c[ks][2], srcA + 2);
        float w3 = __shfl_sync(0xffffffffu, c[ks][3], srcA + 2);
        uint32_t a0 = to_tf32(odd ? v1 : v0);
        uint32_t a1 = to_tf32(odd ? v3 : v2);
        uint32_t a2 = to_tf32(odd ? w1 : w0);
        uint32_t a3 = to_tf32(odd ? w3 : w2);
        #pragma unroll
        for (int nt = 0; nt < 8; nt++) {
            uint32_t b0 = Xt[nt * 8 + qd][ks * 8 + qq];
            uint32_t b1 = Xt[nt * 8 + qd][ks * 8 + qq + 4];
            mma_tf32_r(o[nt], a0, a1, a2, a3, b0, b1);
        }
    }

    // ---- epilogue: normalize rows, write fp32 ----
    const int r0 = mrow + qd, r1 = r0 + 8;
    #pragma unroll
    for (int nt = 0; nt < 8; nt++) {
        int col = nt * 8 + 2 * qq;
        if (r0 < WIN) {
            float2 v = {o[nt][0] * inv0, o[nt][1] * inv0};
            *reinterpret_cast<float2*>(obase + (size_t)r0 * (RATE * DMODEL) + col) = v;
        }
        if (r1 < WIN) {
            float2 v = {o[nt][2] * inv1, o[nt][3] * inv1};
            *reinterpret_cast<float2*>(obase + (size_t)r1 * (RATE * DMODEL) + col) = v;
        }
    }
}

// ---------------------------------------------------------------------------
// Launch: proj1 (tf32 mma) -> mma attention -> proj2 (tf32 mma)
// ---------------------------------------------------------------------------
extern "C" void kernel_launch(void* const* d_in, const int* in_sizes, int n_in,
                              void* d_out, int out_size) {
    const float* emb = (const float*)d_in[0];
    const float* Wq  = (const float*)d_in[1];
    const float* bq  = (const float*)d_in[2];
    const float* Wo  = (const float*)d_in[3];
    const float* bo  = (const float*)d_in[4];
    float* outp = (float*)d_out;

    float *qbuf = nullptr, *abuf = nullptr;
    cudaGetSymbolAddress((void**)&qbuf, g_q);
    cudaGetSymbolAddress((void**)&abuf, g_att);

    const int smemBytes = 64 * 1024;
    static bool attrSet = false;
    if (!attrSet) {
        cudaFuncSetAttribute(gemm_tf32_kernel,
                             cudaFuncAttributeMaxDynamicSharedMemorySize, smemBytes);
        attrSet = true;
    }

    dim3 ggrid(MROWS / 128, DMODEL / 128);   // (1225, 2)
    gemm_tf32_kernel<<<ggrid, 256, smemBytes>>>(emb, Wq, bq, qbuf);
    attn_mma_kernel<<<BATCH * NSEG * RATE * HEADS, 128>>>(qbuf, abuf);
    gemm_tf32_kernel<<<ggrid, 256, smemBytes>>>(abuf, Wo, bo, outp);
}

// round 4
// speedup vs baseline: 3.5761x; 1.2957x over previous
#include <cuda_runtime.h>
#include <cstddef>
#include <cstdint>

// Problem constants
#define BATCH 32
#define NTOK  4900
#define DMODEL 256
#define HEADS 4
#define DH 64
#define WIN 49
#define RATE 5
#define NSEG 20          // NTOK / (WIN*RATE)
#define MROWS (BATCH*NTOK)   // 156800
#define GK 256

__device__ float g_q[(size_t)MROWS * DMODEL];
__device__ float g_att[(size_t)MROWS * DMODEL];

__device__ __forceinline__ uint32_t to_tf32(float x) {
    uint32_t y;
    asm("cvt.rna.tf32.f32 %0, %1;" : "=r"(y) : "f"(x));
    return y;
}

__device__ __forceinline__ void mma_tf32_r(float* c,
                                           uint32_t a0, uint32_t a1, uint32_t a2, uint32_t a3,
                                           uint32_t b0, uint32_t b1) {
    asm volatile(
        "mma.sync.aligned.m16n8k8.row.col.f32.tf32.tf32.f32 "
        "{%0,%1,%2,%3}, {%4,%5,%6,%7}, {%8,%9}, {%0,%1,%2,%3};\n"
        : "+f"(c[0]), "+f"(c[1]), "+f"(c[2]), "+f"(c[3])
        : "r"(a0), "r"(a1), "r"(a2), "r"(a3), "r"(b0), "r"(b1));
}

// ---------------------------------------------------------------------------
// TF32 GEMM, plain padded smem + cp.async + LDS.32 fragment gather.
//   C[m,n] = sum_k A[m,k]*Wt[n,k] + bias[n].  BM=BN=128, BK=32, 256 thr.
//   smem row stride = 36 words  ->  frag-gather banks (4*qd+qq) all distinct.
// ---------------------------------------------------------------------------
#define ASTR 36
#define TILE_WORDS (128 * ASTR)     // 4608

__global__ __launch_bounds__(256, 2)
void gemm_tf32_kernel(const float* __restrict__ A,
                      const float* __restrict__ Wt,
                      const float* __restrict__ bias,
                      float* __restrict__ C) {
    extern __shared__ float smem[];
    float* As0 = smem;
    float* As1 = smem + TILE_WORDS;
    float* Bs0 = smem + 2 * TILE_WORDS;
    float* Bs1 = smem + 3 * TILE_WORDS;

    const int tid  = threadIdx.x;
    const int warp = tid >> 5, lane = tid & 31;
    const int qd = lane >> 2, qq = lane & 3;
    const int wm = warp >> 2;     // 0..1 -> 64 rows
    const int wn = warp & 3;      // 0..3 -> 32 cols
    const int mBase = blockIdx.x * 128;
    const int nBase = blockIdx.y * 128;

    const float* Ab = A + (size_t)mBase * GK;
    const float* Wb = Wt + (size_t)nBase * GK;

    float c[4][4][4];
    #pragma unroll
    for (int i = 0; i < 4; i++)
        #pragma unroll
        for (int j = 0; j < 4; j++)
            #pragma unroll
            for (int r = 0; r < 4; r++) c[i][j][r] = 0.f;

    // per-thread copy slots: idx = l*256+tid -> row m (0..127), kq (0..7)
    auto issue = [&](float* Ad, float* Bd, int kc) {
        #pragma unroll
        for (int l = 0; l < 4; l++) {
            int idx = l * 256 + tid;
            int m   = idx >> 3;
            int kq  = idx & 7;
            uint32_t da = (uint32_t)__cvta_generic_to_shared(&Ad[m * ASTR + kq * 4]);
            const float* sa = Ab + (size_t)m * GK + kc * 32 + kq * 4;
            asm volatile("cp.async.cg.shared.global [%0], [%1], 16;\n" :: "r"(da), "l"(sa));
            uint32_t db = (uint32_t)__cvta_generic_to_shared(&Bd[m * ASTR + kq * 4]);
            const float* sb = Wb + (size_t)m * GK + kc * 32 + kq * 4;
            asm volatile("cp.async.cg.shared.global [%0], [%1], 16;\n" :: "r"(db), "l"(sb));
        }
        asm volatile("cp.async.commit_group;\n");
    };

    issue(As0, Bs0, 0);

    const int aRow = wm * 64 + qd;
    const int bRow = wn * 32 + qd;

    #pragma unroll 1
    for (int kc = 0; kc < 8; kc++) {
        const bool even = !(kc & 1);
        const float* Ac = even ? As0 : As1;
        const float* Bc = even ? Bs0 : Bs1;

        if (kc < 7) {
            issue(even ? As1 : As0, even ? Bs1 : Bs0, kc + 1);
            asm volatile("cp.async.wait_group 1;\n");
        } else {
            asm volatile("cp.async.wait_group 0;\n");
        }
        __syncthreads();

        #pragma unroll
        for (int ks = 0; ks < 4; ks++) {
            uint32_t af[4][4];
            #pragma unroll
            for (int i = 0; i < 4; i++) {
                const float* p0 = &Ac[(aRow + i * 16) * ASTR + ks * 8 + qq];
                af[i][0] = to_tf32(p0[0]);
                af[i][2] = to_tf32(p0[4]);
                af[i][1] = to_tf32(p0[8 * ASTR]);
                af[i][3] = to_tf32(p0[8 * ASTR + 4]);
            }
            uint32_t bf[4][2];
            #pragma unroll
            for (int j = 0; j < 4; j++) {
                const float* pb = &Bc[(bRow + j * 8) * ASTR + ks * 8 + qq];
                bf[j][0] = to_tf32(pb[0]);
                bf[j][1] = to_tf32(pb[4]);
            }
            #pragma unroll
            for (int i = 0; i < 4; i++)
                #pragma unroll
                for (int j = 0; j < 4; j++)
                    mma_tf32_r(c[i][j], af[i][0], af[i][1], af[i][2], af[i][3],
                               bf[j][0], bf[j][1]);
        }
        __syncthreads();
    }

    // Epilogue: add bias, write fp32
    #pragma unroll
    for (int j = 0; j < 4; j++) {
        int col = nBase + wn * 32 + j * 8 + (lane & 3) * 2;
        float b0 = bias[col], b1 = bias[col + 1];
        #pragma unroll
        for (int i = 0; i < 4; i++) {
            int row0 = mBase + wm * 64 + i * 16 + (lane >> 2);
            float2 v0 = {c[i][j][0] + b0, c[i][j][1] + b1};
            float2 v1 = {c[i][j][2] + b0, c[i][j][3] + b1};
            *reinterpret_cast<float2*>(C + (size_t)row0 * GK + col) = v0;
            *reinterpret_cast<float2*>(C + (size_t)(row0 + 8) * GK + col) = v1;
        }
    }
}

// ---------------------------------------------------------------------------
// Tensor-core attention (unchanged from R3): one block per (b,g,r,h).
// ---------------------------------------------------------------------------
__global__ __launch_bounds__(128)
void attn_mma_kernel(const float* __restrict__ q, float* __restrict__ out) {
    __shared__ uint32_t Xs[64][68];
    __shared__ uint32_t Xt[64][68];

    int idx = blockIdx.x;
    int h  = idx & 3;
    int r  = (idx >> 2) % RATE;
    int gg = (idx / (RATE * HEADS)) % NSEG;
    int b  = idx / (RATE * HEADS * NSEG);

    const size_t rowBase = ((size_t)b * NTOK + (size_t)gg * (WIN * RATE) + r);
    const float* base = q + rowBase * DMODEL + h * DH;
    float* obase = out + rowBase * DMODEL + h * DH;

    const int tid  = threadIdx.x;
    const int warp = tid >> 5, lane = tid & 31;
    const int qd = lane >> 2, qq = lane & 3;

    for (int t = tid; t < 15 * 68; t += 128) {
        int rr = t / 68;
        Xs[49 + rr][t - rr * 68] = 0;
    }
    for (int t = tid; t < 64 * 15; t += 128) {
        int d = t / 15;
        Xt[d][49 + (t - d * 15)] = 0;
    }

    for (int t = tid; t < WIN * 16; t += 128) {
        int row = t >> 4, c4 = t & 15;
        float4 v = *reinterpret_cast<const float4*>(
            base + (size_t)row * (RATE * DMODEL) + c4 * 4);
        uint32_t u0 = to_tf32(v.x), u1 = to_tf32(v.y);
        uint32_t u2 = to_tf32(v.z), u3 = to_tf32(v.w);
        *reinterpret_cast<uint4*>(&Xs[row][c4 * 4]) = make_uint4(u0, u1, u2, u3);
        Xt[c4 * 4 + 0][row] = u0;
        Xt[c4 * 4 + 1][row] = u1;
        Xt[c4 * 4 + 2][row] = u2;
        Xt[c4 * 4 + 3][row] = u3;
    }
    __syncthreads();

    const int mrow = warp * 16;

    float c[8][4];
    #pragma unroll
    for (int nt = 0; nt < 8; nt++)
        #pragma unroll
        for (int k = 0; k < 4; k++) c[nt][k] = 0.f;

    #pragma unroll
    for (int ks = 0; ks < 8; ks++) {
        uint32_t a0 = Xs[mrow + qd][ks * 8 + qq];
        uint32_t a1 = Xs[mrow + qd + 8][ks * 8 + qq];
        uint32_t a2 = Xs[mrow + qd][ks * 8 + qq + 4];
        uint32_t a3 = Xs[mrow + qd + 8][ks * 8 + qq + 4];
        #pragma unroll
        for (int nt = 0; nt < 8; nt++) {
            uint32_t b0 = Xs[nt * 8 + qd][ks * 8 + qq];
            uint32_t b1 = Xs[nt * 8 + qd][ks * 8 + qq + 4];
            mma_tf32_r(c[nt], a0, a1, a2, a3, b0, b1);
        }
    }

    const float scale = 0.125f;
    const float NEG = __int_as_float(0xff800000);
    float m0 = NEG, m1 = NEG;
    #pragma unroll
    for (int nt = 0; nt < 8; nt++) {
        #pragma unroll
        for (int par = 0; par < 2; par++) {
            int j = nt * 8 + 2 * qq + par;
            float v0 = (j < WIN) ? c[nt][par] * scale : NEG;
            float v1 = (j < WIN) ? c[nt][par + 2] * scale : NEG;
            c[nt][par] = v0;
            c[nt][par + 2] = v1;
            m0 = fmaxf(m0, v0);
            m1 = fmaxf(m1, v1);
        }
    }
    m0 = fmaxf(m0, __shfl_xor_sync(0xffffffffu, m0, 1));
    m0 = fmaxf(m0, __shfl_xor_sync(0xffffffffu, m0, 2));
    m1 = fmaxf(m1, __shfl_xor_sync(0xffffffffu, m1, 1));
    m1 = fmaxf(m1, __shfl_xor_sync(0xffffffffu, m1, 2));

    float s0 = 0.f, s1 = 0.f;
    #pragma unroll
    for (int nt = 0; nt < 8; nt++) {
        #pragma unroll
        for (int par = 0; par < 2; par++) {
            float e0 = __expf(c[nt][par] - m0);
            float e1 = __expf(c[nt][par + 2] - m1);
            c[nt][par] = e0;
            c[nt][par + 2] = e1;
            s0 += e0;
            s1 += e1;
        }
    }
    s0 += __shfl_xor_sync(0xffffffffu, s0, 1);
    s0 += __shfl_xor_sync(0xffffffffu, s0, 2);
    s1 += __shfl_xor_sync(0xffffffffu, s1, 1);
    s1 += __shfl_xor_sync(0xffffffffu, s1, 2);
    float inv0 = 1.f / s0, inv1 = 1.f / s1;

    float o[8][4];
    #pragma unroll
    for (int nt = 0; nt < 8; nt++)
        #pragma unroll
        for (int k = 0; k < 4; k++) o[nt][k] = 0.f;

    const int srcA = (lane & ~3) + (qq >> 1);
    const bool odd = (qq & 1);

    #pragma unroll
    for (int ks = 0; ks < 8; ks++) {
        float v0 = __shfl_sync(0xffffffffu, c[ks][0], srcA);
        float v1 = __shfl_sync(0xffffffffu, c[ks][1], srcA);
        float v2 = __shfl_sync(0xffffffffu, c[ks][2], srcA);
        float v3 = __shfl_sync(0xffffffffu, c[ks][3], srcA);
        float w0 = __shfl_sync(0xffffffffu, c[ks][0], srcA + 2);
        float w1 = __shfl_sync(0xffffffffu, c[ks][1], srcA + 2);
        float w2 = __shfl_sync(0xffffffffu, c[ks][2], srcA + 2);
        float w3 = __shfl_sync(0xffffffffu, c[ks][3], srcA + 2);
        uint32_t a0 = to_tf32(odd ? v1 : v0);
        uint32_t a1 = to_tf32(odd ? v3 : v2);
        uint32_t a2 = to_tf32(odd ? w1 : w0);
        uint32_t a3 = to_tf32(odd ? w3 : w2);
        #pragma unroll
        for (int nt = 0; nt < 8; nt++) {
            uint32_t b0 = Xt[nt * 8 + qd][ks * 8 + qq];
            uint32_t b1 = Xt[nt * 8 + qd][ks * 8 + qq + 4];
            mma_tf32_r(o[nt], a0, a1, a2, a3, b0, b1);
        }
    }

    const int r0 = mrow + qd, r1 = r0 + 8;
    #pragma unroll
    for (int nt = 0; nt < 8; nt++) {
        int col = nt * 8 + 2 * qq;
        if (r0 < WIN) {
            float2 v = {o[nt][0] * inv0, o[nt][1] * inv0};
            *reinterpret_cast<float2*>(obase + (size_t)r0 * (RATE * DMODEL) + col) = v;
        }
        if (r1 < WIN) {
            float2 v = {o[nt][2] * inv1, o[nt][3] * inv1};
            *reinterpret_cast<float2*>(obase + (size_t)r1 * (RATE * DMODEL) + col) = v;
        }
    }
}

// ---------------------------------------------------------------------------
// Launch
// ---------------------------------------------------------------------------
extern "C" void kernel_launch(void* const* d_in, const int* in_sizes, int n_in,
                              void* d_out, int out_size) {
    const float* emb = (const float*)d_in[0];
    const float* Wq  = (const float*)d_in[1];
    const float* bq  = (const float*)d_in[2];
    const float* Wo  = (const float*)d_in[3];
    const float* bo  = (const float*)d_in[4];
    float* outp = (float*)d_out;

    float *qbuf = nullptr, *abuf = nullptr;
    cudaGetSymbolAddress((void**)&qbuf, g_q);
    cudaGetSymbolAddress((void**)&abuf, g_att);

    const int smemBytes = 4 * TILE_WORDS * 4;   // 73728
    static bool attrSet = false;
    if (!attrSet) {
        cudaFuncSetAttribute(gemm_tf32_kernel,
                             cudaFuncAttributeMaxDynamicSharedMemorySize, smemBytes);
        attrSet = true;
    }

    dim3 ggrid(MROWS / 128, DMODEL / 128);   // (1225, 2)
    gemm_tf32_kernel<<<ggrid, 256, smemBytes>>>(emb, Wq, bq, qbuf);
    attn_mma_kernel<<<BATCH * NSEG * RATE * HEADS, 128>>>(qbuf, abuf);
    gemm_tf32_kernel<<<ggrid, 256, smemBytes>>>(abuf, Wo, bo, outp);
}